// round 4
// baseline (speedup 1.0000x reference)
#include <cuda_runtime.h>
#include <math.h>

#define NCOMP 20
#define T_MAX_GUESS 100.0f   // only a speed hint; correctness guarded by fallback
#define WIN 128              // window floats (32 lanes x float4)

__global__ void __launch_bounds__(256) markov_kernel(
        const int* __restrict__ src,
        const int* __restrict__ dst,
        const float* __restrict__ t,
        const float* __restrict__ x_pad,
        const float* __restrict__ t_pad,
        const float* __restrict__ emb_src,
        const float* __restrict__ emb_dst,
        const float* __restrict__ alpha_p,
        const float* __restrict__ beta_p,
        float* __restrict__ out,
        int E, int L)
{
    const int lane = threadIdx.x & 31;
    const int e = (blockIdx.x * blockDim.x + threadIdx.x) >> 5;
    if (e >= E) return;

    const float tq = __ldg(&t[e]);
    const float* __restrict__ row = t_pad + (size_t)e * L;

    // ---- kick off embedding gathers early (independent of search) ----
    const int s = __ldg(&src[e]);
    const int d = __ldg(&dst[e]);
    float av = 0.0f, bv = 0.0f;
    if (lane < NCOMP) {
        av = __ldg(&emb_src[(size_t)s * NCOMP + lane]);
        bv = __ldg(&emb_dst[(size_t)d * NCOMP + lane]);
    }

    // ---- interpolation guess + contiguous 128-float window ----
    int g = (int)(tq * ((float)L / T_MAX_GUESS));
    int lo = g - (WIN / 2);
    lo = max(lo, 0);
    lo = min(lo, L - WIN);   // L >= WIN here (L = 2048)
    lo &= ~3;                // 16-byte align the float4 window base

    const float4 q = *reinterpret_cast<const float4*>(row + lo + lane * 4);
    unsigned m0 = __ballot_sync(0xffffffffu, q.x < tq);
    unsigned m1 = __ballot_sync(0xffffffffu, q.y < tq);
    unsigned m2 = __ballot_sync(0xffffffffu, q.z < tq);
    unsigned m3 = __ballot_sync(0xffffffffu, q.w < tq);
    int cw = __popc(m0) + __popc(m1) + __popc(m2) + __popc(m3);

    const bool valid = (cw > 0 || lo == 0) && (cw < WIN || lo + WIN == L);

    int cnt;
    float t_last = 0.0f;
    if (valid) {
        cnt = lo + cw;
        if (cnt > 0) {
            // fetch row[cnt-1] from the window via shuffle (no memory reload)
            int off = cnt - 1 - lo;              // in [0, WIN)
            int sl  = off >> 2;                  // source lane (warp-uniform)
            int cp  = off & 3;                   // component  (warp-uniform)
            float sel = (cp == 0) ? q.x : (cp == 1) ? q.y : (cp == 2) ? q.z : q.w;
            t_last = __shfl_sync(0xffffffffu, sel, sl);
        }
    } else {
        // ---- generic 2-round 32-ary search (rare; correct for any input) ----
        const int chunkw = L >> 5;               // 64
        float vb = __ldg(&row[(lane + 1) * chunkw - 1]);
        unsigned b = __ballot_sync(0xffffffffu, vb < tq);
        int chunk = __popc(b);
        if (chunk >= 32) {
            cnt = L;
        } else {
            const float* cbase = row + chunk * chunkw;   // 64-float aligned
            float2 p = *reinterpret_cast<const float2*>(cbase + lane * 2);
            unsigned b0 = __ballot_sync(0xffffffffu, p.x < tq);
            unsigned b1 = __ballot_sync(0xffffffffu, p.y < tq);
            cnt = chunk * chunkw + __popc(b0) + __popc(b1);
        }
        if (cnt > 0) t_last = __ldg(&row[cnt - 1]);
    }

    const bool has_prev = (cnt > 0);
    const int idx = has_prev ? (cnt - 1) : 0;

    // ---- dot-product reduction (lanes 0..19 hold products) ----
    float prod = av * bv;
    #pragma unroll
    for (int off = 16; off > 0; off >>= 1)
        prod += __shfl_xor_sync(0xffffffffu, prod, off);

    if (lane == 0) {
        float dot = prod;
        float base = fmaxf(dot, 0.0f) + log1pf(expf(-fabsf(dot)));  // softplus

        float incr = 0.0f;
        if (has_prev) {
            float x_raw = __ldg(&x_pad[(size_t)e * L + idx]);
            float z = (x_raw - 0.5f) * 4.0f;        // (x - MEAN)/VAR, VAR=0.25
            float sig = 1.0f / (1.0f + expf(-z));
            float alpha = __ldg(alpha_p);
            float beta  = __ldg(beta_p);
            incr = alpha * sig * expf(-beta * (tq - t_last));
        }
        out[e] = base + incr;
    }
}

extern "C" void kernel_launch(void* const* d_in, const int* in_sizes, int n_in,
                              void* d_out, int out_size)
{
    const int*   src     = (const int*)  d_in[0];
    const int*   dst     = (const int*)  d_in[1];
    const float* t       = (const float*)d_in[2];
    const float* x_pad   = (const float*)d_in[3];
    const float* t_pad   = (const float*)d_in[4];
    const float* emb_src = (const float*)d_in[5];
    const float* emb_dst = (const float*)d_in[6];
    const float* alpha   = (const float*)d_in[7];
    const float* beta    = (const float*)d_in[8];
    float* out = (float*)d_out;

    const int E = in_sizes[2];
    const int L = in_sizes[4] / E;        // 2048

    // warp per event: 256 threads = 8 events/block
    const int threads = 256;
    const int blocks = (E * 32 + threads - 1) / threads;   // 2048 blocks
    markov_kernel<<<blocks, threads>>>(src, dst, t, x_pad, t_pad,
                                       emb_src, emb_dst, alpha, beta,
                                       out, E, L);
}

// round 5
// speedup vs baseline: 1.0753x; 1.0753x over previous
#include <cuda_runtime.h>
#include <math.h>

#define NCOMP 20
#define T_MAX_GUESS 100.0f   // speed hint only; fallback guarantees correctness
#define WIN 128              // window floats per event

// 4 events per warp, 8 lanes per event.
__global__ void __launch_bounds__(128) markov_kernel(
        const int* __restrict__ src,
        const int* __restrict__ dst,
        const float* __restrict__ t,
        const float* __restrict__ x_pad,
        const float* __restrict__ t_pad,
        const float* __restrict__ emb_src,
        const float* __restrict__ emb_dst,
        const float* __restrict__ alpha_p,
        const float* __restrict__ beta_p,
        float* __restrict__ out,
        int E, int L)
{
    const int lane = threadIdx.x & 31;
    const int sub  = lane >> 3;          // event slot in warp (0..3)
    const int sl   = lane & 7;           // sublane within event (0..7)
    const int warp = (blockIdx.x * blockDim.x + threadIdx.x) >> 5;
    const int e_raw = warp * 4 + sub;
    const bool live = (e_raw < E);
    const int e = live ? e_raw : (E - 1);        // clamp: keep warp converged

    const float tq = __ldg(&t[e]);
    const float* __restrict__ row = t_pad + (size_t)e * L;

    // ---- embedding gathers (independent of search; issue early) ----
    const int s = __ldg(&src[e]);
    const int d = __ldg(&dst[e]);
    const float* es = emb_src + (size_t)s * NCOMP;
    const float* ed = emb_dst + (size_t)d * NCOMP;
    float a0 = __ldg(&es[sl]),     b0 = __ldg(&ed[sl]);
    float a1 = __ldg(&es[sl + 8]), b1 = __ldg(&ed[sl + 8]);
    float a2 = 0.0f, b2 = 0.0f;
    if (sl < 4) { a2 = __ldg(&es[sl + 16]); b2 = __ldg(&ed[sl + 16]); }

    // ---- interpolation guess, 128-float window, 4 independent float4/lane ----
    int g = (int)(tq * ((float)L / T_MAX_GUESS));
    int lo = g - (WIN / 2);
    lo = max(lo, 0);
    lo = min(lo, L - WIN);
    lo &= ~3;                                    // float4 alignment

    const float* wbase = row + lo;
    // element widx = k*32 + sl*4 + c  (each k-step: 128B coalesced across 8 lanes)
    float4 q0 = *reinterpret_cast<const float4*>(wbase + 0 * 32 + sl * 4);
    float4 q1 = *reinterpret_cast<const float4*>(wbase + 1 * 32 + sl * 4);
    float4 q2 = *reinterpret_cast<const float4*>(wbase + 2 * 32 + sl * 4);
    float4 q3 = *reinterpret_cast<const float4*>(wbase + 3 * 32 + sl * 4);

    int c = (q0.x < tq) + (q0.y < tq) + (q0.z < tq) + (q0.w < tq)
          + (q1.x < tq) + (q1.y < tq) + (q1.z < tq) + (q1.w < tq)
          + (q2.x < tq) + (q2.y < tq) + (q2.z < tq) + (q2.w < tq)
          + (q3.x < tq) + (q3.y < tq) + (q3.z < tq) + (q3.w < tq);

    // ---- fused 8-lane segment reduction: window count + embedding dot ----
    float prod = a0 * b0 + a1 * b1 + a2 * b2;
    #pragma unroll
    for (int off = 1; off < 8; off <<= 1) {
        c    += __shfl_xor_sync(0xffffffffu, c, off);
        prod += __shfl_xor_sync(0xffffffffu, prod, off);
    }
    // c, prod now uniform within each 8-lane group

    int cnt = lo + c;

    // ---- t_last from window registers (one shuffle; group-uniform selectors) ----
    int offw = min(max(cnt - 1 - lo, 0), WIN - 1);
    int k  = offw >> 5;                          // which float4
    int ls = (offw >> 2) & 7;                    // source sublane
    int cp = offw & 3;                           // component
    float4 qs = (k == 0) ? q0 : (k == 1) ? q1 : (k == 2) ? q2 : q3;
    float sel = (cp == 0) ? qs.x : (cp == 1) ? qs.y : (cp == 2) ? qs.z : qs.w;
    float t_last = __shfl_sync(0xffffffffu, sel, sub * 8 + ls);

    // ---- validity: window must bracket the boundary ----
    const bool valid = (c > 0 || lo == 0) && (c < WIN || lo + WIN == L);
    if (__any_sync(0xffffffffu, !valid)) {
        if (!valid) {                            // rare: scalar binary search (all 8 lanes redundant)
            int loB = 0, hiB = L;
            while (loB < hiB) {
                int mid = (loB + hiB) >> 1;
                if (__ldg(&row[mid]) < tq) loB = mid + 1; else hiB = mid;
            }
            cnt = loB;
            t_last = (cnt > 0) ? __ldg(&row[cnt - 1]) : 0.0f;
        }
    }

    const bool has_prev = (cnt > 0);
    const int idx = has_prev ? (cnt - 1) : 0;

    if (sl == 0 && live) {
        float dot = prod;
        float base = fmaxf(dot, 0.0f) + log1pf(expf(-fabsf(dot)));  // softplus

        float incr = 0.0f;
        if (has_prev) {
            float x_raw = __ldg(&x_pad[(size_t)e * L + idx]);
            float z = (x_raw - 0.5f) * 4.0f;          // (x - MEAN)/VAR, VAR=0.25
            float sig = 1.0f / (1.0f + expf(-z));
            float alpha = __ldg(alpha_p);
            float beta  = __ldg(beta_p);
            incr = alpha * sig * expf(-beta * (tq - t_last));
        }
        out[e] = base + incr;
    }
}

extern "C" void kernel_launch(void* const* d_in, const int* in_sizes, int n_in,
                              void* d_out, int out_size)
{
    const int*   src     = (const int*)  d_in[0];
    const int*   dst     = (const int*)  d_in[1];
    const float* t       = (const float*)d_in[2];
    const float* x_pad   = (const float*)d_in[3];
    const float* t_pad   = (const float*)d_in[4];
    const float* emb_src = (const float*)d_in[5];
    const float* emb_dst = (const float*)d_in[6];
    const float* alpha   = (const float*)d_in[7];
    const float* beta    = (const float*)d_in[8];
    float* out = (float*)d_out;

    const int E = in_sizes[2];
    const int L = in_sizes[4] / E;       // 2048

    // 4 events per warp, 128-thread blocks -> 16 events/block
    const int threads = 128;
    const int events_per_block = (threads / 32) * 4;
    const int blocks = (E + events_per_block - 1) / events_per_block;  // 1024
    markov_kernel<<<blocks, threads>>>(src, dst, t, x_pad, t_pad,
                                       emb_src, emb_dst, alpha, beta,
                                       out, E, L);
}